// round 10
// baseline (speedup 1.0000x reference)
#include <cuda_runtime.h>
#include <math.h>
#include <stdint.h>

#define N_ROWS 8192
#define N_CODES 8192
#define D_DIM 256
#define INV_T 100.0f
#define EPS_F 1e-5f

#define KA 2709.0f
#define KC 86698.0f
#define SC_HH (65536.0f / (KA * KC))
#define SC_MID (256.0f / (KA * KC))
#define RECHECK_MARGIN 0.02f

// ---------------- device scratch ----------------
__device__ float g_dist[(size_t)N_ROWS * (size_t)N_CODES];  // d' = -2xc + cn2 (no xn2)
__device__ __align__(16) float g_cn2[N_CODES];
__device__ float g_avgp[N_CODES];
__device__ float g_sq_sum;
__device__ float g_sent_sum;
// per-(row, 128-col-tile) softmax partials: {min, argmin(bits), S, ET} ; 64 tiles/row
__device__ __align__(16) float4 g_part[(size_t)N_ROWS * 64];
// int8 hi/lo operands, packed 4 k per uint32, natural k order. A pre-scaled by -2.
__device__ __align__(16) uint32_t g_Ah[(size_t)N_ROWS * D_DIM / 4];
__device__ __align__(16) uint32_t g_Al[(size_t)N_ROWS * D_DIM / 4];
__device__ __align__(16) uint32_t g_Bh[(size_t)N_CODES * D_DIM / 4];
__device__ __align__(16) uint32_t g_Bl[(size_t)N_CODES * D_DIM / 4];

// ---------------- helpers ----------------
__device__ __forceinline__ uint32_t smem_u32(const void* p) {
    uint32_t a;
    asm("{ .reg .u64 t; cvta.to.shared.u64 t, %1; cvt.u32.u64 %0, t; }" : "=r"(a) : "l"(p));
    return a;
}
__device__ __forceinline__ void cp16(uint32_t dst, const void* src) {
    asm volatile("cp.async.cg.shared.global [%0], [%1], 16;" :: "r"(dst), "l"(src) : "memory");
}
__device__ __forceinline__ void imma(int* d, const uint32_t* a, const uint32_t* b) {
    asm volatile("mma.sync.aligned.m16n8k32.row.col.s32.s8.s8.s32 "
                 "{%0,%1,%2,%3}, {%4,%5,%6,%7}, {%8,%9}, {%0,%1,%2,%3};"
                 : "+r"(d[0]), "+r"(d[1]), "+r"(d[2]), "+r"(d[3])
                 : "r"(a[0]), "r"(a[1]), "r"(a[2]), "r"(a[3]), "r"(b[0]), "r"(b[1]));
}
__device__ __forceinline__ uint32_t quant_pack_hi(const int* v) {
    uint32_t r = 0;
    #pragma unroll
    for (int j = 0; j < 4; j++) {
        int ah = (v[j] + 128) >> 8;
        r |= ((uint32_t)(ah & 0xFF)) << (8 * j);
    }
    return r;
}
__device__ __forceinline__ uint32_t quant_pack_lo(const int* v) {
    uint32_t r = 0;
    #pragma unroll
    for (int j = 0; j < 4; j++) {
        int ah = (v[j] + 128) >> 8;
        int al = v[j] - (ah << 8);
        r |= ((uint32_t)(al & 0xFF)) << (8 * j);
    }
    return r;
}

// ---------------- zero accumulators ----------------
__global__ void zero_kernel() {
    int tid = blockIdx.x * blockDim.x + threadIdx.x;
    if (tid < N_CODES) g_avgp[tid] = 0.0f;
    if (tid == 0) { g_sq_sum = 0.0f; g_sent_sum = 0.0f; }
}

// ---------------- codebook squared norms ----------------
__global__ void rownorm_kernel(const float* __restrict__ C) {
    int warp = threadIdx.x >> 5;
    int lane = threadIdx.x & 31;
    int row = blockIdx.x * 8 + warp;
    const float4* s4 = reinterpret_cast<const float4*>(C + (size_t)row * D_DIM);
    float4 a = s4[lane];
    float4 b = s4[lane + 32];
    float s = a.x*a.x + a.y*a.y + a.z*a.z + a.w*a.w
            + b.x*b.x + b.y*b.y + b.z*b.z + b.w*b.w;
    #pragma unroll
    for (int o = 16; o > 0; o >>= 1) s += __shfl_down_sync(0xffffffffu, s, o);
    if (lane == 0) g_cn2[row] = s;
}

// ---------------- preconvert to int8 hi/lo ----------------
__global__ __launch_bounds__(256) void preconv_kernel(const float* __restrict__ X,
                                                      const float* __restrict__ C) {
    int i = blockIdx.x * blockDim.x + threadIdx.x;
    const float4 x = reinterpret_cast<const float4*>(X)[i];
    int v[4];
    v[0] = max(-32512, min(32512, __float2int_rn(-2.0f * x.x * KA)));
    v[1] = max(-32512, min(32512, __float2int_rn(-2.0f * x.y * KA)));
    v[2] = max(-32512, min(32512, __float2int_rn(-2.0f * x.z * KA)));
    v[3] = max(-32512, min(32512, __float2int_rn(-2.0f * x.w * KA)));
    g_Ah[i] = quant_pack_hi(v);
    g_Al[i] = quant_pack_lo(v);
    const float4 c = reinterpret_cast<const float4*>(C)[i];
    v[0] = max(-32512, min(32512, __float2int_rn(c.x * KC)));
    v[1] = max(-32512, min(32512, __float2int_rn(c.y * KC)));
    v[2] = max(-32512, min(32512, __float2int_rn(c.z * KC)));
    v[3] = max(-32512, min(32512, __float2int_rn(c.w * KC)));
    g_Bh[i] = quant_pack_hi(v);
    g_Bl[i] = quant_pack_lo(v);
}

// ---------------- 3xINT8 IMMA GEMM: d' = -2xc + cn2 ----------------
// CTA tile 128x128, BK=32, 8 warps (2x4), warp tile 64x32, 1 CTA/SM.
// 4-stage cp.async ring (16KB/stage), one __syncthreads per chunk.
#define STG_BYTES 16384
#define AHS 0
#define ALS 4096
#define BHS 8192
#define BLS 12288
#define STAGE_STRIDE 132
#define GEMM_SMEM_BYTES (128 * STAGE_STRIDE * 4)   // 67584 > 4*16384

__global__ __launch_bounds__(256, 1) void gemm_mma_kernel() {
    extern __shared__ char dsm[];
    float* smf = reinterpret_cast<float*>(dsm);   // epilogue stage (overlaps ring)
    const uint32_t smem_base = smem_u32(dsm);
    const int tid  = threadIdx.x;
    const int lane = tid & 31;
    const int wid  = tid >> 5;
    const int wm   = wid & 1;          // 2 x 64 rows
    const int wn   = wid >> 1;         // 4 x 32 cols
    const int q    = lane & 3;
    const int lr   = lane >> 2;
    const int rowBase = blockIdx.y * 128;
    const int colBase = blockIdx.x * 128;

    // fill pointers: each thread covers row tid>>1, half tid&1 of all 4 tiles
    const int fr = tid >> 1, fh = tid & 1;
    const char* pAh = reinterpret_cast<const char*>(g_Ah) + (size_t)(rowBase + fr) * 256 + fh * 16;
    const char* pAl = reinterpret_cast<const char*>(g_Al) + (size_t)(rowBase + fr) * 256 + fh * 16;
    const char* pBh = reinterpret_cast<const char*>(g_Bh) + (size_t)(colBase + fr) * 256 + fh * 16;
    const char* pBl = reinterpret_cast<const char*>(g_Bl) + (size_t)(colBase + fr) * 256 + fh * 16;
    const uint32_t dA = (uint32_t)(fr * 32 + fh * 16);

    int ahh[4][4][4], amid[4][4][4];
    #pragma unroll
    for (int mf = 0; mf < 4; mf++)
        #pragma unroll
        for (int nf = 0; nf < 4; nf++)
            #pragma unroll
            for (int j = 0; j < 4; j++) { ahh[mf][nf][j] = 0; amid[mf][nf][j] = 0; }

    uint32_t aOff[4], bOff[4];
    #pragma unroll
    for (int mf = 0; mf < 4; mf++)
        aOff[mf] = (uint32_t)((wm * 64 + mf * 16 + lr) * 32 + q * 8);
    #pragma unroll
    for (int nf = 0; nf < 4; nf++)
        bOff[nf] = (uint32_t)((wn * 32 + nf * 8 + lr) * 32 + q * 8);

    #define FILLC(s) do { \
        uint32_t sb = smem_base + (uint32_t)(s) * STG_BYTES; \
        cp16(sb + AHS + dA, pAh); \
        cp16(sb + ALS + dA, pAl); \
        cp16(sb + BHS + dA, pBh); \
        cp16(sb + BLS + dA, pBl); \
        asm volatile("cp.async.commit_group;" ::: "memory"); \
        pAh += 32; pAl += 32; pBh += 32; pBl += 32; \
    } while (0)

    FILLC(0); FILLC(1); FILLC(2);

    #pragma unroll
    for (int ch = 0; ch < 8; ch++) {
        asm volatile("cp.async.wait_group 2;" ::: "memory");
        __syncthreads();
        if (ch < 5) { FILLC((ch + 3) & 3); }
        else        { asm volatile("cp.async.commit_group;" ::: "memory"); }

        const char* base = dsm + (ch & 3) * STG_BYTES;
        // sweep 1: ah x bh -> hh
        uint32_t ah[4][4], bh[4][2];
        #pragma unroll
        for (int mf = 0; mf < 4; mf++) {
            uint2 h0 = *reinterpret_cast<const uint2*>(base + AHS + aOff[mf]);
            uint2 h1 = *reinterpret_cast<const uint2*>(base + AHS + aOff[mf] + 8 * 32);
            ah[mf][0] = h0.x; ah[mf][1] = h1.x; ah[mf][2] = h0.y; ah[mf][3] = h1.y;
        }
        #pragma unroll
        for (int nf = 0; nf < 4; nf++) {
            uint2 wh = *reinterpret_cast<const uint2*>(base + BHS + bOff[nf]);
            bh[nf][0] = wh.x; bh[nf][1] = wh.y;
        }
        #pragma unroll
        for (int nf = 0; nf < 4; nf++)
            #pragma unroll
            for (int mf = 0; mf < 4; mf++)
                imma(ahh[mf][nf], ah[mf], bh[nf]);
        // sweep 2: ah x bl -> mid (ah dies after)
        uint32_t bl[4][2];
        #pragma unroll
        for (int nf = 0; nf < 4; nf++) {
            uint2 wl = *reinterpret_cast<const uint2*>(base + BLS + bOff[nf]);
            bl[nf][0] = wl.x; bl[nf][1] = wl.y;
        }
        #pragma unroll
        for (int nf = 0; nf < 4; nf++)
            #pragma unroll
            for (int mf = 0; mf < 4; mf++)
                imma(amid[mf][nf], ah[mf], bl[nf]);
        // sweep 3: al x bh -> mid
        uint32_t al[4][4];
        #pragma unroll
        for (int mf = 0; mf < 4; mf++) {
            uint2 l0 = *reinterpret_cast<const uint2*>(base + ALS + aOff[mf]);
            uint2 l1 = *reinterpret_cast<const uint2*>(base + ALS + aOff[mf] + 8 * 32);
            al[mf][0] = l0.x; al[mf][1] = l1.x; al[mf][2] = l0.y; al[mf][3] = l1.y;
        }
        #pragma unroll
        for (int nf = 0; nf < 4; nf++)
            #pragma unroll
            for (int mf = 0; mf < 4; mf++)
                imma(amid[mf][nf], al[mf], bh[nf]);
    }
    #undef FILLC

    // ---- epilogue: convert + stage (with cn2), store, per-tile partials ----
    __syncthreads();    // ring dead; reuse smem as float stage [128][132]
    #pragma unroll
    for (int mf = 0; mf < 4; mf++) {
        int r0 = wm * 64 + mf * 16 + lr;
        #pragma unroll
        for (int nf = 0; nf < 4; nf++) {
            int c0 = wn * 32 + nf * 8 + 2 * q;
            float cn0 = __ldg(&g_cn2[colBase + c0]);
            float cn1 = __ldg(&g_cn2[colBase + c0 + 1]);
            float d00 = fmaf(SC_HH, (float)ahh[mf][nf][0], fmaf(SC_MID, (float)amid[mf][nf][0], cn0));
            float d01 = fmaf(SC_HH, (float)ahh[mf][nf][1], fmaf(SC_MID, (float)amid[mf][nf][1], cn1));
            float d10 = fmaf(SC_HH, (float)ahh[mf][nf][2], fmaf(SC_MID, (float)amid[mf][nf][2], cn0));
            float d11 = fmaf(SC_HH, (float)ahh[mf][nf][3], fmaf(SC_MID, (float)amid[mf][nf][3], cn1));
            *reinterpret_cast<float2*>(smf + r0 * STAGE_STRIDE + c0) = make_float2(d00, d01);
            *reinterpret_cast<float2*>(smf + (r0 + 8) * STAGE_STRIDE + c0) = make_float2(d10, d11);
        }
    }
    __syncthreads();

    // coalesced stores: 4096 float4 / 256 threads = 16 each
    #pragma unroll
    for (int i = 0; i < 16; i++) {
        int idx = tid + 256 * i;
        int r  = idx >> 5;
        int c4 = idx & 31;
        float4 v = *reinterpret_cast<const float4*>(smf + r * STAGE_STRIDE + c4 * 4);
        *reinterpret_cast<float4*>(g_dist + (size_t)(rowBase + r) * N_CODES + colBase + c4 * 4) = v;
    }

    // partials: warp wid -> rows wid*16..+15, full warp per 128-col row
    for (int it = 0; it < 16; it++) {
        int r = wid * 16 + it;
        float4 v = *reinterpret_cast<const float4*>(smf + r * STAGE_STRIDE + lane * 4);
        float m = v.x; int ii = 0;
        if (v.y < m) { m = v.y; ii = 1; }
        if (v.z < m) { m = v.z; ii = 2; }
        if (v.w < m) { m = v.w; ii = 3; }
        int bc = lane * 4 + ii;
        #pragma unroll
        for (int o = 1; o < 32; o <<= 1) {
            float om = __shfl_xor_sync(0xffffffffu, m, o);
            int   oc = __shfl_xor_sync(0xffffffffu, bc, o);
            if (om < m || (om == m && oc < bc)) { m = om; bc = oc; }
        }
        float S = 0.0f, ET = 0.0f;
        {
            float t, e;
            t = (m - v.x) * INV_T; if (t > -40.0f) { e = __expf(t); S += e; ET += e * t; }
            t = (m - v.y) * INV_T; if (t > -40.0f) { e = __expf(t); S += e; ET += e * t; }
            t = (m - v.z) * INV_T; if (t > -40.0f) { e = __expf(t); S += e; ET += e * t; }
            t = (m - v.w) * INV_T; if (t > -40.0f) { e = __expf(t); S += e; ET += e * t; }
        }
        #pragma unroll
        for (int o = 1; o < 32; o <<= 1) {
            S  += __shfl_xor_sync(0xffffffffu, S, o);
            ET += __shfl_xor_sync(0xffffffffu, ET, o);
        }
        if (lane == 0)
            g_part[(size_t)(rowBase + r) * 64 + blockIdx.x] =
                make_float4(m, __int_as_float(colBase + bc), S, ET);
    }
}

// ---------------- merge pass: one warp per row; exact argmin recheck ----------------
__global__ __launch_bounds__(256) void rowmerge_kernel(const float* __restrict__ X,
                                                       const float* __restrict__ C,
                                                       float* __restrict__ out,
                                                       int idx_off) {
    const int lane = threadIdx.x & 31;
    const int row  = blockIdx.x * 8 + (threadIdx.x >> 5);

    float4 p[2];
    #pragma unroll
    for (int j = 0; j < 2; j++) p[j] = g_part[(size_t)row * 64 + j * 32 + lane];

    float m, S, ET; int ai;
    m = p[0].x; ai = __float_as_int(p[0].y); S = p[0].z; ET = p[0].w;
    {
        float om = p[1].x; int oi = __float_as_int(p[1].y);
        float oS = p[1].z, oE = p[1].w;
        bool take = (om < m) || (om == m && oi < ai);
        float mw = take ? om : m, ml = take ? m : om;
        float Sw = take ? oS : S, Sl = take ? S : oS;
        float Ew = take ? oE : ET, El = take ? ET : oE;
        int   iw = take ? oi : ai;
        float dd = (mw - ml) * INV_T;
        float f = __expf(dd);
        m = mw; S = Sw + f * Sl; ET = Ew + f * (El + Sl * dd); ai = iw;
    }
    #pragma unroll
    for (int o = 1; o < 32; o <<= 1) {
        float om = __shfl_xor_sync(0xffffffffu, m, o);
        int   oi = __shfl_xor_sync(0xffffffffu, ai, o);
        float oS = __shfl_xor_sync(0xffffffffu, S, o);
        float oE = __shfl_xor_sync(0xffffffffu, ET, o);
        bool take = (om < m) || (om == m && oi < ai);
        float mw = take ? om : m, ml = take ? m : om;
        float Sw = take ? oS : S, Sl = take ? S : oS;
        float Ew = take ? oE : ET, El = take ? ET : oE;
        int   iw = take ? oi : ai;
        float dd = (mw - ml) * INV_T;
        float f = __expf(dd);
        m = mw; S = Sw + f * Sl; ET = Ew + f * (El + Sl * dd); ai = iw;
    }
    const float dmin = m;
    const float invS = 1.0f / S;

    const float4* x4 = reinterpret_cast<const float4*>(X + (size_t)row * D_DIM);
    float4 xr0 = x4[lane], xr1 = x4[lane + 32];

    const float thr  = dmin + 0.40f;
    const float thr2 = dmin + RECHECK_MARGIN;
    float bestd = 3.4e38f;
    int   besti = 0x7fffffff;
    #pragma unroll
    for (int j = 0; j < 2; j++) {
        unsigned mask = __ballot_sync(0xffffffffu, p[j].x < thr);
        while (mask) {
            int t = __ffs(mask) - 1;
            mask &= mask - 1;
            int tile = j * 32 + t;
            const float4* drow = reinterpret_cast<const float4*>(
                g_dist + (size_t)row * N_CODES + tile * 128);
            float4 v = drow[lane];
            float vv[4] = { v.x, v.y, v.z, v.w };
            #pragma unroll
            for (int s = 0; s < 4; s++) {
                float tt = (dmin - vv[s]) * INV_T;
                if (tt > -40.0f) {
                    float e = __expf(tt);
                    float pp = e * invS;
                    if (pp > 1e-10f) atomicAdd(&g_avgp[tile * 128 + lane * 4 + s], pp);
                }
            }
            #pragma unroll
            for (int s = 0; s < 4; s++) {
                unsigned cm = __ballot_sync(0xffffffffu, vv[s] < thr2);
                while (cm) {
                    int src = __ffs(cm) - 1;
                    cm &= cm - 1;
                    int k = tile * 128 + src * 4 + s;
                    const float4* c4 = reinterpret_cast<const float4*>(C + (size_t)k * D_DIM);
                    float4 ca = c4[lane], cb = c4[lane + 32];
                    float dot = ca.x*xr0.x + ca.y*xr0.y + ca.z*xr0.z + ca.w*xr0.w
                              + cb.x*xr1.x + cb.y*xr1.y + cb.z*xr1.z + cb.w*xr1.w;
                    #pragma unroll
                    for (int o = 1; o < 32; o <<= 1)
                        dot += __shfl_xor_sync(0xffffffffu, dot, o);
                    float ed = __ldg(&g_cn2[k]) - 2.0f * dot;
                    if (ed < bestd || (ed == bestd && k < besti)) { bestd = ed; besti = k; }
                }
            }
        }
    }
    const int amin = besti;

    const float4* c4 = reinterpret_cast<const float4*>(C + (size_t)amin * D_DIM);
    float4* o4 = reinterpret_cast<float4*>(out + (size_t)row * D_DIM);
    float sq = 0.0f;
    {
        float4 c = c4[lane], o;
        float d0 = c.x - xr0.x, d1 = c.y - xr0.y, d2 = c.z - xr0.z, d3 = c.w - xr0.w;
        o.x = xr0.x + d0; o.y = xr0.y + d1; o.z = xr0.z + d2; o.w = xr0.w + d3;
        o4[lane] = o;
        sq += d0*d0 + d1*d1 + d2*d2 + d3*d3;
        c = c4[lane + 32];
        d0 = c.x - xr1.x; d1 = c.y - xr1.y; d2 = c.z - xr1.z; d3 = c.w - xr1.w;
        o.x = xr1.x + d0; o.y = xr1.y + d1; o.z = xr1.z + d2; o.w = xr1.w + d3;
        o4[lane + 32] = o;
        sq += d0*d0 + d1*d1 + d2*d2 + d3*d3;
    }
    #pragma unroll
    for (int o = 16; o > 0; o >>= 1) sq += __shfl_down_sync(0xffffffffu, sq, o);
    if (lane == 0) {
        atomicAdd(&g_sq_sum, sq);
        atomicAdd(&g_sent_sum, logf(S) - ET * invS);
        out[idx_off + row] = (float)amin;
    }
}

// ---------------- finalize ----------------
__global__ __launch_bounds__(256) void finalize_kernel(float* __restrict__ out, int loss_off) {
    __shared__ float redf[256];
    const int tid = threadIdx.x;
    float h = 0.0f;
    const float invN = 1.0f / (float)N_ROWS;
    for (int k = tid; k < N_CODES; k += 256) {
        float a = g_avgp[k] * invN;
        h -= a * logf(a + EPS_F);
    }
    redf[tid] = h;
    __syncthreads();
    #pragma unroll
    for (int o = 128; o > 0; o >>= 1) { if (tid < o) redf[tid] += redf[tid + o]; __syncthreads(); }
    if (tid == 0) {
        float avg_entropy = redf[0];
        float sample_entropy = g_sent_sum * invN;
        float recon = 1.25f * g_sq_sum / ((float)N_ROWS * (float)D_DIM);
        float entropy_loss = 0.1f * (sample_entropy - avg_entropy);
        out[loss_off] = recon + entropy_loss;
    }
}

// ---------------- launch ----------------
extern "C" void kernel_launch(void* const* d_in, const int* in_sizes, int n_in,
                              void* d_out, int out_size) {
    const float* X = (const float*)d_in[0];
    const float* C = (const float*)d_in[1];
    float* out = (float*)d_out;

    const int q_elems  = N_ROWS * D_DIM;
    const int loss_off = q_elems;
    const int idx_off  = q_elems + 1;

    static int smem_set = 0;
    if (!smem_set) {
        cudaFuncSetAttribute(gemm_mma_kernel, cudaFuncAttributeMaxDynamicSharedMemorySize,
                             GEMM_SMEM_BYTES);
        smem_set = 1;
    }

    zero_kernel<<<(N_CODES + 255) / 256, 256>>>();
    rownorm_kernel<<<N_CODES / 8, 256>>>(C);
    preconv_kernel<<<(N_ROWS * D_DIM / 4) / 256, 256>>>(X, C);

    dim3 gemm_grid(N_CODES / 128, N_ROWS / 128);
    gemm_mma_kernel<<<gemm_grid, 256, GEMM_SMEM_BYTES>>>();

    rowmerge_kernel<<<N_ROWS / 8, 256>>>(X, C, out, idx_off);
    finalize_kernel<<<1, 256>>>(out, loss_off);
}

// round 11
// speedup vs baseline: 1.0038x; 1.0038x over previous
#include <cuda_runtime.h>
#include <math.h>
#include <stdint.h>

#define N_ROWS 8192
#define N_CODES 8192
#define D_DIM 256
#define INV_T 100.0f
#define EPS_F 1e-5f

#define KA 2709.0f
#define KC 86698.0f
#define SC_HH (65536.0f / (KA * KC))
#define SC_MID (256.0f / (KA * KC))
#define RECHECK_MARGIN 0.02f

// ---------------- device scratch ----------------
__device__ float g_dist[(size_t)N_ROWS * (size_t)N_CODES];  // d' = -2xc + cn2 (no xn2)
__device__ __align__(16) float g_cn2[N_CODES];
__device__ float g_avgp[N_CODES];
__device__ float g_sq_sum;
__device__ float g_sent_sum;
// per-(row, 128-col-tile) softmax partials: {min, argmin(bits), S, ET} ; 64 tiles/row
__device__ __align__(16) float4 g_part[(size_t)N_ROWS * 64];
// int8 hi/lo operands, packed 4 k per uint32, natural k order. A pre-scaled by -2.
__device__ __align__(16) uint32_t g_Ah[(size_t)N_ROWS * D_DIM / 4];
__device__ __align__(16) uint32_t g_Al[(size_t)N_ROWS * D_DIM / 4];
__device__ __align__(16) uint32_t g_Bh[(size_t)N_CODES * D_DIM / 4];
__device__ __align__(16) uint32_t g_Bl[(size_t)N_CODES * D_DIM / 4];

// ---------------- helpers ----------------
__device__ __forceinline__ uint32_t smem_u32(const void* p) {
    uint32_t a;
    asm("{ .reg .u64 t; cvta.to.shared.u64 t, %1; cvt.u32.u64 %0, t; }" : "=r"(a) : "l"(p));
    return a;
}
__device__ __forceinline__ void cp16(uint32_t dst, const void* src) {
    asm volatile("cp.async.cg.shared.global [%0], [%1], 16;" :: "r"(dst), "l"(src) : "memory");
}
__device__ __forceinline__ void imma(int* d, const uint32_t* a, const uint32_t* b) {
    asm volatile("mma.sync.aligned.m16n8k32.row.col.s32.s8.s8.s32 "
                 "{%0,%1,%2,%3}, {%4,%5,%6,%7}, {%8,%9}, {%0,%1,%2,%3};"
                 : "+r"(d[0]), "+r"(d[1]), "+r"(d[2]), "+r"(d[3])
                 : "r"(a[0]), "r"(a[1]), "r"(a[2]), "r"(a[3]), "r"(b[0]), "r"(b[1]));
}
__device__ __forceinline__ uint32_t quant_pack_hi(const int* v) {
    uint32_t r = 0;
    #pragma unroll
    for (int j = 0; j < 4; j++) {
        int ah = (v[j] + 128) >> 8;
        r |= ((uint32_t)(ah & 0xFF)) << (8 * j);
    }
    return r;
}
__device__ __forceinline__ uint32_t quant_pack_lo(const int* v) {
    uint32_t r = 0;
    #pragma unroll
    for (int j = 0; j < 4; j++) {
        int ah = (v[j] + 128) >> 8;
        int al = v[j] - (ah << 8);
        r |= ((uint32_t)(al & 0xFF)) << (8 * j);
    }
    return r;
}

// ---------------- zero accumulators ----------------
__global__ void zero_kernel() {
    int tid = blockIdx.x * blockDim.x + threadIdx.x;
    if (tid < N_CODES) g_avgp[tid] = 0.0f;
    if (tid == 0) { g_sq_sum = 0.0f; g_sent_sum = 0.0f; }
}

// ---------------- codebook squared norms ----------------
__global__ void rownorm_kernel(const float* __restrict__ C) {
    int warp = threadIdx.x >> 5;
    int lane = threadIdx.x & 31;
    int row = blockIdx.x * 8 + warp;
    const float4* s4 = reinterpret_cast<const float4*>(C + (size_t)row * D_DIM);
    float4 a = s4[lane];
    float4 b = s4[lane + 32];
    float s = a.x*a.x + a.y*a.y + a.z*a.z + a.w*a.w
            + b.x*b.x + b.y*b.y + b.z*b.z + b.w*b.w;
    #pragma unroll
    for (int o = 16; o > 0; o >>= 1) s += __shfl_down_sync(0xffffffffu, s, o);
    if (lane == 0) g_cn2[row] = s;
}

// ---------------- preconvert to int8 hi/lo ----------------
__global__ __launch_bounds__(256) void preconv_kernel(const float* __restrict__ X,
                                                      const float* __restrict__ C) {
    int i = blockIdx.x * blockDim.x + threadIdx.x;
    const float4 x = reinterpret_cast<const float4*>(X)[i];
    int v[4];
    v[0] = max(-32512, min(32512, __float2int_rn(-2.0f * x.x * KA)));
    v[1] = max(-32512, min(32512, __float2int_rn(-2.0f * x.y * KA)));
    v[2] = max(-32512, min(32512, __float2int_rn(-2.0f * x.z * KA)));
    v[3] = max(-32512, min(32512, __float2int_rn(-2.0f * x.w * KA)));
    g_Ah[i] = quant_pack_hi(v);
    g_Al[i] = quant_pack_lo(v);
    const float4 c = reinterpret_cast<const float4*>(C)[i];
    v[0] = max(-32512, min(32512, __float2int_rn(c.x * KC)));
    v[1] = max(-32512, min(32512, __float2int_rn(c.y * KC)));
    v[2] = max(-32512, min(32512, __float2int_rn(c.z * KC)));
    v[3] = max(-32512, min(32512, __float2int_rn(c.w * KC)));
    g_Bh[i] = quant_pack_hi(v);
    g_Bl[i] = quant_pack_lo(v);
}

// ---------------- 3xINT8 IMMA GEMM: d' = -2xc + cn2 ----------------
// CTA tile 128x128, BK=32, 8 warps (2x4), warp tile 64x32, 1 CTA/SM.
// 4-stage cp.async ring (16KB/stage), one __syncthreads per chunk.
#define STG_BYTES 16384
#define AHS 0
#define ALS 4096
#define BHS 8192
#define BLS 12288
#define STAGE_STRIDE 132
#define GEMM_SMEM_BYTES (128 * STAGE_STRIDE * 4)   // 67584 > 4*16384

__global__ __launch_bounds__(256, 1) void gemm_mma_kernel() {
    extern __shared__ char dsm[];
    float* smf = reinterpret_cast<float*>(dsm);   // epilogue stage (overlaps ring)
    const uint32_t smem_base = smem_u32(dsm);
    const int tid  = threadIdx.x;
    const int lane = tid & 31;
    const int wid  = tid >> 5;
    const int wm   = wid & 1;          // 2 x 64 rows
    const int wn   = wid >> 1;         // 4 x 32 cols
    const int q    = lane & 3;
    const int lr   = lane >> 2;
    const int rowBase = blockIdx.y * 128;
    const int colBase = blockIdx.x * 128;

    // fill pointers: each thread covers row tid>>1, half tid&1 of all 4 tiles
    const int fr = tid >> 1, fh = tid & 1;
    const char* pAh = reinterpret_cast<const char*>(g_Ah) + (size_t)(rowBase + fr) * 256 + fh * 16;
    const char* pAl = reinterpret_cast<const char*>(g_Al) + (size_t)(rowBase + fr) * 256 + fh * 16;
    const char* pBh = reinterpret_cast<const char*>(g_Bh) + (size_t)(colBase + fr) * 256 + fh * 16;
    const char* pBl = reinterpret_cast<const char*>(g_Bl) + (size_t)(colBase + fr) * 256 + fh * 16;
    const uint32_t dA = (uint32_t)(fr * 32 + fh * 16);

    int ahh[4][4][4], amid[4][4][4];
    #pragma unroll
    for (int mf = 0; mf < 4; mf++)
        #pragma unroll
        for (int nf = 0; nf < 4; nf++)
            #pragma unroll
            for (int j = 0; j < 4; j++) { ahh[mf][nf][j] = 0; amid[mf][nf][j] = 0; }

    uint32_t aOff[4], bOff[4];
    #pragma unroll
    for (int mf = 0; mf < 4; mf++)
        aOff[mf] = (uint32_t)((wm * 64 + mf * 16 + lr) * 32 + q * 8);
    #pragma unroll
    for (int nf = 0; nf < 4; nf++)
        bOff[nf] = (uint32_t)((wn * 32 + nf * 8 + lr) * 32 + q * 8);

    #define FILLC(s) do { \
        uint32_t sb = smem_base + (uint32_t)(s) * STG_BYTES; \
        cp16(sb + AHS + dA, pAh); \
        cp16(sb + ALS + dA, pAl); \
        cp16(sb + BHS + dA, pBh); \
        cp16(sb + BLS + dA, pBl); \
        asm volatile("cp.async.commit_group;" ::: "memory"); \
        pAh += 32; pAl += 32; pBh += 32; pBl += 32; \
    } while (0)

    FILLC(0); FILLC(1); FILLC(2);

    #pragma unroll
    for (int ch = 0; ch < 8; ch++) {
        asm volatile("cp.async.wait_group 2;" ::: "memory");
        __syncthreads();
        if (ch < 5) { FILLC((ch + 3) & 3); }
        else        { asm volatile("cp.async.commit_group;" ::: "memory"); }

        const char* base = dsm + (ch & 3) * STG_BYTES;
        // sweep 1: ah x bh -> hh
        uint32_t ah[4][4], bh[4][2];
        #pragma unroll
        for (int mf = 0; mf < 4; mf++) {
            uint2 h0 = *reinterpret_cast<const uint2*>(base + AHS + aOff[mf]);
            uint2 h1 = *reinterpret_cast<const uint2*>(base + AHS + aOff[mf] + 8 * 32);
            ah[mf][0] = h0.x; ah[mf][1] = h1.x; ah[mf][2] = h0.y; ah[mf][3] = h1.y;
        }
        #pragma unroll
        for (int nf = 0; nf < 4; nf++) {
            uint2 wh = *reinterpret_cast<const uint2*>(base + BHS + bOff[nf]);
            bh[nf][0] = wh.x; bh[nf][1] = wh.y;
        }
        #pragma unroll
        for (int nf = 0; nf < 4; nf++)
            #pragma unroll
            for (int mf = 0; mf < 4; mf++)
                imma(ahh[mf][nf], ah[mf], bh[nf]);
        // sweep 2: ah x bl -> mid (ah dies after)
        uint32_t bl[4][2];
        #pragma unroll
        for (int nf = 0; nf < 4; nf++) {
            uint2 wl = *reinterpret_cast<const uint2*>(base + BLS + bOff[nf]);
            bl[nf][0] = wl.x; bl[nf][1] = wl.y;
        }
        #pragma unroll
        for (int nf = 0; nf < 4; nf++)
            #pragma unroll
            for (int mf = 0; mf < 4; mf++)
                imma(amid[mf][nf], ah[mf], bl[nf]);
        // sweep 3: al x bh -> mid
        uint32_t al[4][4];
        #pragma unroll
        for (int mf = 0; mf < 4; mf++) {
            uint2 l0 = *reinterpret_cast<const uint2*>(base + ALS + aOff[mf]);
            uint2 l1 = *reinterpret_cast<const uint2*>(base + ALS + aOff[mf] + 8 * 32);
            al[mf][0] = l0.x; al[mf][1] = l1.x; al[mf][2] = l0.y; al[mf][3] = l1.y;
        }
        #pragma unroll
        for (int nf = 0; nf < 4; nf++)
            #pragma unroll
            for (int mf = 0; mf < 4; mf++)
                imma(amid[mf][nf], al[mf], bh[nf]);
    }
    #undef FILLC

    // ---- epilogue: convert + stage (with cn2), store, per-tile partials ----
    __syncthreads();    // ring dead; reuse smem as float stage [128][132]
    #pragma unroll
    for (int mf = 0; mf < 4; mf++) {
        int r0 = wm * 64 + mf * 16 + lr;
        #pragma unroll
        for (int nf = 0; nf < 4; nf++) {
            int c0 = wn * 32 + nf * 8 + 2 * q;
            float cn0 = __ldg(&g_cn2[colBase + c0]);
            float cn1 = __ldg(&g_cn2[colBase + c0 + 1]);
            float d00 = fmaf(SC_HH, (float)ahh[mf][nf][0], fmaf(SC_MID, (float)amid[mf][nf][0], cn0));
            float d01 = fmaf(SC_HH, (float)ahh[mf][nf][1], fmaf(SC_MID, (float)amid[mf][nf][1], cn1));
            float d10 = fmaf(SC_HH, (float)ahh[mf][nf][2], fmaf(SC_MID, (float)amid[mf][nf][2], cn0));
            float d11 = fmaf(SC_HH, (float)ahh[mf][nf][3], fmaf(SC_MID, (float)amid[mf][nf][3], cn1));
            *reinterpret_cast<float2*>(smf + r0 * STAGE_STRIDE + c0) = make_float2(d00, d01);
            *reinterpret_cast<float2*>(smf + (r0 + 8) * STAGE_STRIDE + c0) = make_float2(d10, d11);
        }
    }
    __syncthreads();

    // coalesced stores: 4096 float4 / 256 threads = 16 each
    #pragma unroll
    for (int i = 0; i < 16; i++) {
        int idx = tid + 256 * i;
        int r  = idx >> 5;
        int c4 = idx & 31;
        float4 v = *reinterpret_cast<const float4*>(smf + r * STAGE_STRIDE + c4 * 4);
        *reinterpret_cast<float4*>(g_dist + (size_t)(rowBase + r) * N_CODES + colBase + c4 * 4) = v;
    }

    // partials: warp wid -> rows wid*16..+15, full warp per 128-col row
    for (int it = 0; it < 16; it++) {
        int r = wid * 16 + it;
        float4 v = *reinterpret_cast<const float4*>(smf + r * STAGE_STRIDE + lane * 4);
        float m = v.x; int ii = 0;
        if (v.y < m) { m = v.y; ii = 1; }
        if (v.z < m) { m = v.z; ii = 2; }
        if (v.w < m) { m = v.w; ii = 3; }
        int bc = lane * 4 + ii;
        #pragma unroll
        for (int o = 1; o < 32; o <<= 1) {
            float om = __shfl_xor_sync(0xffffffffu, m, o);
            int   oc = __shfl_xor_sync(0xffffffffu, bc, o);
            if (om < m || (om == m && oc < bc)) { m = om; bc = oc; }
        }
        float S = 0.0f, ET = 0.0f;
        {
            float t, e;
            t = (m - v.x) * INV_T; if (t > -40.0f) { e = __expf(t); S += e; ET += e * t; }
            t = (m - v.y) * INV_T; if (t > -40.0f) { e = __expf(t); S += e; ET += e * t; }
            t = (m - v.z) * INV_T; if (t > -40.0f) { e = __expf(t); S += e; ET += e * t; }
            t = (m - v.w) * INV_T; if (t > -40.0f) { e = __expf(t); S += e; ET += e * t; }
        }
        #pragma unroll
        for (int o = 1; o < 32; o <<= 1) {
            S  += __shfl_xor_sync(0xffffffffu, S, o);
            ET += __shfl_xor_sync(0xffffffffu, ET, o);
        }
        if (lane == 0)
            g_part[(size_t)(rowBase + r) * 64 + blockIdx.x] =
                make_float4(m, __int_as_float(colBase + bc), S, ET);
    }
}

// ---------------- merge pass: one warp per row; exact argmin recheck ----------------
__global__ __launch_bounds__(256) void rowmerge_kernel(const float* __restrict__ X,
                                                       const float* __restrict__ C,
                                                       float* __restrict__ out,
                                                       int idx_off) {
    const int lane = threadIdx.x & 31;
    const int row  = blockIdx.x * 8 + (threadIdx.x >> 5);

    float4 p[2];
    #pragma unroll
    for (int j = 0; j < 2; j++) p[j] = g_part[(size_t)row * 64 + j * 32 + lane];

    float m, S, ET; int ai;
    m = p[0].x; ai = __float_as_int(p[0].y); S = p[0].z; ET = p[0].w;
    {
        float om = p[1].x; int oi = __float_as_int(p[1].y);
        float oS = p[1].z, oE = p[1].w;
        bool take = (om < m) || (om == m && oi < ai);
        float mw = take ? om : m, ml = take ? m : om;
        float Sw = take ? oS : S, Sl = take ? S : oS;
        float Ew = take ? oE : ET, El = take ? ET : oE;
        int   iw = take ? oi : ai;
        float dd = (mw - ml) * INV_T;
        float f = __expf(dd);
        m = mw; S = Sw + f * Sl; ET = Ew + f * (El + Sl * dd); ai = iw;
    }
    #pragma unroll
    for (int o = 1; o < 32; o <<= 1) {
        float om = __shfl_xor_sync(0xffffffffu, m, o);
        int   oi = __shfl_xor_sync(0xffffffffu, ai, o);
        float oS = __shfl_xor_sync(0xffffffffu, S, o);
        float oE = __shfl_xor_sync(0xffffffffu, ET, o);
        bool take = (om < m) || (om == m && oi < ai);
        float mw = take ? om : m, ml = take ? m : om;
        float Sw = take ? oS : S, Sl = take ? S : oS;
        float Ew = take ? oE : ET, El = take ? ET : oE;
        int   iw = take ? oi : ai;
        float dd = (mw - ml) * INV_T;
        float f = __expf(dd);
        m = mw; S = Sw + f * Sl; ET = Ew + f * (El + Sl * dd); ai = iw;
    }
    const float dmin = m;
    const float invS = 1.0f / S;

    const float4* x4 = reinterpret_cast<const float4*>(X + (size_t)row * D_DIM);
    float4 xr0 = x4[lane], xr1 = x4[lane + 32];

    const float thr  = dmin + 0.40f;
    const float thr2 = dmin + RECHECK_MARGIN;
    float bestd = 3.4e38f;
    int   besti = 0x7fffffff;
    #pragma unroll
    for (int j = 0; j < 2; j++) {
        unsigned mask = __ballot_sync(0xffffffffu, p[j].x < thr);
        while (mask) {
            int t = __ffs(mask) - 1;
            mask &= mask - 1;
            int tile = j * 32 + t;
            const float4* drow = reinterpret_cast<const float4*>(
                g_dist + (size_t)row * N_CODES + tile * 128);
            float4 v = drow[lane];
            float vv[4] = { v.x, v.y, v.z, v.w };
            #pragma unroll
            for (int s = 0; s < 4; s++) {
                float tt = (dmin - vv[s]) * INV_T;
                if (tt > -40.0f) {
                    float e = __expf(tt);
                    float pp = e * invS;
                    if (pp > 1e-10f) atomicAdd(&g_avgp[tile * 128 + lane * 4 + s], pp);
                }
            }
            #pragma unroll
            for (int s = 0; s < 4; s++) {
                unsigned cm = __ballot_sync(0xffffffffu, vv[s] < thr2);
                while (cm) {
                    int src = __ffs(cm) - 1;
                    cm &= cm - 1;
                    int k = tile * 128 + src * 4 + s;
                    const float4* c4 = reinterpret_cast<const float4*>(C + (size_t)k * D_DIM);
                    float4 ca = c4[lane], cb = c4[lane + 32];
                    float dot = ca.x*xr0.x + ca.y*xr0.y + ca.z*xr0.z + ca.w*xr0.w
                              + cb.x*xr1.x + cb.y*xr1.y + cb.z*xr1.z + cb.w*xr1.w;
                    #pragma unroll
                    for (int o = 1; o < 32; o <<= 1)
                        dot += __shfl_xor_sync(0xffffffffu, dot, o);
                    float ed = __ldg(&g_cn2[k]) - 2.0f * dot;
                    if (ed < bestd || (ed == bestd && k < besti)) { bestd = ed; besti = k; }
                }
            }
        }
    }
    const int amin = besti;

    const float4* c4 = reinterpret_cast<const float4*>(C + (size_t)amin * D_DIM);
    float4* o4 = reinterpret_cast<float4*>(out + (size_t)row * D_DIM);
    float sq = 0.0f;
    {
        float4 c = c4[lane], o;
        float d0 = c.x - xr0.x, d1 = c.y - xr0.y, d2 = c.z - xr0.z, d3 = c.w - xr0.w;
        o.x = xr0.x + d0; o.y = xr0.y + d1; o.z = xr0.z + d2; o.w = xr0.w + d3;
        o4[lane] = o;
        sq += d0*d0 + d1*d1 + d2*d2 + d3*d3;
        c = c4[lane + 32];
        d0 = c.x - xr1.x; d1 = c.y - xr1.y; d2 = c.z - xr1.z; d3 = c.w - xr1.w;
        o.x = xr1.x + d0; o.y = xr1.y + d1; o.z = xr1.z + d2; o.w = xr1.w + d3;
        o4[lane + 32] = o;
        sq += d0*d0 + d1*d1 + d2*d2 + d3*d3;
    }
    #pragma unroll
    for (int o = 16; o > 0; o >>= 1) sq += __shfl_down_sync(0xffffffffu, sq, o);
    if (lane == 0) {
        atomicAdd(&g_sq_sum, sq);
        atomicAdd(&g_sent_sum, logf(S) - ET * invS);
        out[idx_off + row] = (float)amin;
    }
}

// ---------------- finalize ----------------
__global__ __launch_bounds__(256) void finalize_kernel(float* __restrict__ out, int loss_off) {
    __shared__ float redf[256];
    const int tid = threadIdx.x;
    float h = 0.0f;
    const float invN = 1.0f / (float)N_ROWS;
    for (int k = tid; k < N_CODES; k += 256) {
        float a = g_avgp[k] * invN;
        h -= a * logf(a + EPS_F);
    }
    redf[tid] = h;
    __syncthreads();
    #pragma unroll
    for (int o = 128; o > 0; o >>= 1) { if (tid < o) redf[tid] += redf[tid + o]; __syncthreads(); }
    if (tid == 0) {
        float avg_entropy = redf[0];
        float sample_entropy = g_sent_sum * invN;
        float recon = 1.25f * g_sq_sum / ((float)N_ROWS * (float)D_DIM);
        float entropy_loss = 0.1f * (sample_entropy - avg_entropy);
        out[loss_off] = recon + entropy_loss;
    }
}

// ---------------- launch ----------------
extern "C" void kernel_launch(void* const* d_in, const int* in_sizes, int n_in,
                              void* d_out, int out_size) {
    const float* X = (const float*)d_in[0];
    const float* C = (const float*)d_in[1];
    float* out = (float*)d_out;

    const int q_elems  = N_ROWS * D_DIM;
    const int loss_off = q_elems;
    const int idx_off  = q_elems + 1;

    static int smem_set = 0;
    if (!smem_set) {
        cudaFuncSetAttribute(gemm_mma_kernel, cudaFuncAttributeMaxDynamicSharedMemorySize,
                             GEMM_SMEM_BYTES);
        smem_set = 1;
    }

    zero_kernel<<<(N_CODES + 255) / 256, 256>>>();
    rownorm_kernel<<<N_CODES / 8, 256>>>(C);
    preconv_kernel<<<(N_ROWS * D_DIM / 4) / 256, 256>>>(X, C);

    dim3 gemm_grid(N_CODES / 128, N_ROWS / 128);
    gemm_mma_kernel<<<gemm_grid, 256, GEMM_SMEM_BYTES>>>();

    rowmerge_kernel<<<N_ROWS / 8, 256>>>(X, C, out, idx_off);
    finalize_kernel<<<1, 256>>>(out, loss_off);
}